// round 1
// baseline (speedup 1.0000x reference)
#include <cuda_runtime.h>
#include <math.h>

// Scratch for the precomputed input projection xU = x @ U + b : [B=256, T=512, K=256] fp32
#define Bsz 256
#define Tsz 512
#define Dsz 256
#define Ksz 256

__device__ float g_xU[Bsz * Tsz * Ksz];   // 128 MB device-global scratch (allowed)

// ---------------------------------------------------------------------------
// Kernel A: xU = X @ U + b
// X: [M=131072, 256] row-major, U: [256, 256] row-major, out: [M, 256]
// Tiling: BM=64, BN=64, BK=16, 256 threads, 4x4 microtile per thread.
// ---------------------------------------------------------------------------
#define BM 64
#define BN 64
#define BK 16

__global__ void __launch_bounds__(256) gemm_xu_kernel(
    const float* __restrict__ X,
    const float* __restrict__ U,
    const float* __restrict__ bias,
    float* __restrict__ out)
{
    __shared__ float As[BK][68];   // padded (68) to break STS bank conflicts; 68*4 % 16 == 0
    __shared__ float Bs[BK][BN];

    const int tid  = threadIdx.x;
    const int tx   = tid & 15;          // col group 0..15
    const int ty   = tid >> 4;          // row group 0..15
    const int row0 = blockIdx.y * BM;
    const int col0 = blockIdx.x * BN;

    // A-tile load mapping: 64 rows x 16 k, one float4 per thread
    const int am = tid >> 2;            // 0..63
    const int ak = (tid & 3) << 2;      // 0,4,8,12
    // B-tile load mapping: 16 k x 64 n, one float4 per thread
    const int bk = tid >> 4;            // 0..15
    const int bn = (tid & 15) << 2;     // 0..60

    float acc[4][4] = {};

    for (int kk = 0; kk < Dsz; kk += BK) {
        float4 a4 = *(const float4*)&X[(size_t)(row0 + am) * Dsz + kk + ak];
        As[ak + 0][am] = a4.x;
        As[ak + 1][am] = a4.y;
        As[ak + 2][am] = a4.z;
        As[ak + 3][am] = a4.w;
        *(float4*)&Bs[bk][bn] = *(const float4*)&U[(size_t)(kk + bk) * Ksz + col0 + bn];
        __syncthreads();

        #pragma unroll
        for (int k = 0; k < BK; k++) {
            float4 a = *(const float4*)&As[k][ty << 2];
            float4 b = *(const float4*)&Bs[k][tx << 2];
            acc[0][0] += a.x * b.x; acc[0][1] += a.x * b.y; acc[0][2] += a.x * b.z; acc[0][3] += a.x * b.w;
            acc[1][0] += a.y * b.x; acc[1][1] += a.y * b.y; acc[1][2] += a.y * b.z; acc[1][3] += a.y * b.w;
            acc[2][0] += a.z * b.x; acc[2][1] += a.z * b.y; acc[2][2] += a.z * b.z; acc[2][3] += a.z * b.w;
            acc[3][0] += a.w * b.x; acc[3][1] += a.w * b.y; acc[3][2] += a.w * b.z; acc[3][3] += a.w * b.w;
        }
        __syncthreads();
    }

    float4 bb = *(const float4*)&bias[col0 + (tx << 2)];
    #pragma unroll
    for (int i = 0; i < 4; i++) {
        float4 o;
        o.x = acc[i][0] + bb.x;
        o.y = acc[i][1] + bb.y;
        o.z = acc[i][2] + bb.z;
        o.w = acc[i][3] + bb.w;
        *(float4*)&out[(size_t)(row0 + (ty << 2) + i) * Ksz + col0 + (tx << 2)] = o;
    }
}

// ---------------------------------------------------------------------------
// Kernel B: recurrence. Batch rows are independent -> no cross-block sync.
// 64 blocks x 256 threads, 4 batch rows per block. h lives in smem (broadcast
// reads), W streamed from L2 each step (64 blocks * 512 * 256KB = 8.6 GB total,
// under the LTS cap). Thread k owns output column k for all 4 rows.
// ---------------------------------------------------------------------------
#define RROWS 4

__global__ void __launch_bounds__(256) rnn_rec_kernel(
    const float* __restrict__ xU,
    const float* __restrict__ W,
    float* __restrict__ out)
{
    __shared__ float hsm[RROWS][Ksz];

    const int k  = threadIdx.x;
    const int b0 = blockIdx.x * RROWS;

    #pragma unroll
    for (int r = 0; r < RROWS; r++) hsm[r][k] = 0.0f;
    __syncthreads();

    for (int t = 0; t < Tsz; t++) {
        // start accumulators at the precomputed input projection
        float acc0 = xU[((size_t)(b0 + 0) * Tsz + t) * Ksz + k];
        float acc1 = xU[((size_t)(b0 + 1) * Tsz + t) * Ksz + k];
        float acc2 = xU[((size_t)(b0 + 2) * Tsz + t) * Ksz + k];
        float acc3 = xU[((size_t)(b0 + 3) * Tsz + t) * Ksz + k];

        #pragma unroll 4
        for (int d = 0; d < Ksz; d += 4) {
            float w0 = W[(size_t)(d + 0) * Ksz + k];
            float w1 = W[(size_t)(d + 1) * Ksz + k];
            float w2 = W[(size_t)(d + 2) * Ksz + k];
            float w3 = W[(size_t)(d + 3) * Ksz + k];
            float4 h0 = *(const float4*)&hsm[0][d];
            float4 h1 = *(const float4*)&hsm[1][d];
            float4 h2 = *(const float4*)&hsm[2][d];
            float4 h3 = *(const float4*)&hsm[3][d];
            acc0 += h0.x * w0; acc0 += h0.y * w1; acc0 += h0.z * w2; acc0 += h0.w * w3;
            acc1 += h1.x * w0; acc1 += h1.y * w1; acc1 += h1.z * w2; acc1 += h1.w * w3;
            acc2 += h2.x * w0; acc2 += h2.y * w1; acc2 += h2.z * w2; acc2 += h2.w * w3;
            acc3 += h3.x * w0; acc3 += h3.y * w1; acc3 += h3.z * w2; acc3 += h3.w * w3;
        }

        __syncthreads();   // everyone done READING hsm (step t-1 state)
        hsm[0][k] = tanhf(acc0);
        hsm[1][k] = tanhf(acc1);
        hsm[2][k] = tanhf(acc2);
        hsm[3][k] = tanhf(acc3);
        __syncthreads();   // everyone done WRITING hsm (step t state)
    }

    #pragma unroll
    for (int r = 0; r < RROWS; r++)
        out[(size_t)(b0 + r) * Ksz + k] = hsm[r][k];
}

// ---------------------------------------------------------------------------
// Launch
// ---------------------------------------------------------------------------
extern "C" void kernel_launch(void* const* d_in, const int* in_sizes, int n_in,
                              void* d_out, int out_size)
{
    const float* x    = (const float*)d_in[0];   // [256, 512, 256]
    const float* U    = (const float*)d_in[1];   // [256, 256]
    const float* W    = (const float*)d_in[2];   // [256, 256]
    const float* bias = (const float*)d_in[3];   // [256]
    float* out        = (float*)d_out;           // [256, 1, 256]

    float* xU;
    cudaGetSymbolAddress((void**)&xU, g_xU);

    // Kernel A: input projection (M = B*T = 131072 rows)
    dim3 gridA(Ksz / BN, (Bsz * Tsz) / BM);   // (4, 2048)
    gemm_xu_kernel<<<gridA, 256>>>(x, U, bias, xU);

    // Kernel B: sequential recurrence, batch-partitioned
    rnn_rec_kernel<<<Bsz / RROWS, 256>>>(xU, W, out);
}

// round 2
// speedup vs baseline: 2.9125x; 2.9125x over previous
#include <cuda_runtime.h>
#include <math.h>
#include <stdint.h>

#define Bsz 256
#define Tsz 512
#define Dsz 256
#define Ksz 256

__device__ float g_xU[Bsz * Tsz * Ksz];   // 128 MB scratch for xU = x@U + b

// ---------------------------------------------------------------------------
// Kernel A: xU = X @ U + b   (unchanged from R1)
// ---------------------------------------------------------------------------
#define BM 64
#define BN 64
#define BK 16

__global__ void __launch_bounds__(256) gemm_xu_kernel(
    const float* __restrict__ X,
    const float* __restrict__ U,
    const float* __restrict__ bias,
    float* __restrict__ out)
{
    __shared__ float As[BK][68];
    __shared__ float Bs[BK][BN];

    const int tid  = threadIdx.x;
    const int tx   = tid & 15;
    const int ty   = tid >> 4;
    const int row0 = blockIdx.y * BM;
    const int col0 = blockIdx.x * BN;

    const int am = tid >> 2;
    const int ak = (tid & 3) << 2;
    const int bk = tid >> 4;
    const int bn = (tid & 15) << 2;

    float acc[4][4] = {};

    for (int kk = 0; kk < Dsz; kk += BK) {
        float4 a4 = *(const float4*)&X[(size_t)(row0 + am) * Dsz + kk + ak];
        As[ak + 0][am] = a4.x;
        As[ak + 1][am] = a4.y;
        As[ak + 2][am] = a4.z;
        As[ak + 3][am] = a4.w;
        *(float4*)&Bs[bk][bn] = *(const float4*)&U[(size_t)(kk + bk) * Ksz + col0 + bn];
        __syncthreads();

        #pragma unroll
        for (int k = 0; k < BK; k++) {
            float4 a = *(const float4*)&As[k][ty << 2];
            float4 b = *(const float4*)&Bs[k][tx << 2];
            acc[0][0] += a.x * b.x; acc[0][1] += a.x * b.y; acc[0][2] += a.x * b.z; acc[0][3] += a.x * b.w;
            acc[1][0] += a.y * b.x; acc[1][1] += a.y * b.y; acc[1][2] += a.y * b.z; acc[1][3] += a.y * b.w;
            acc[2][0] += a.z * b.x; acc[2][1] += a.z * b.y; acc[2][2] += a.z * b.z; acc[2][3] += a.z * b.w;
            acc[3][0] += a.w * b.x; acc[3][1] += a.w * b.y; acc[3][2] += a.w * b.z; acc[3][3] += a.w * b.w;
        }
        __syncthreads();
    }

    float4 bb = *(const float4*)&bias[col0 + (tx << 2)];
    #pragma unroll
    for (int i = 0; i < 4; i++) {
        float4 o;
        o.x = acc[i][0] + bb.x;
        o.y = acc[i][1] + bb.y;
        o.z = acc[i][2] + bb.z;
        o.w = acc[i][3] + bb.w;
        *(float4*)&out[(size_t)(row0 + (ty << 2) + i) * Ksz + col0 + (tx << 2)] = o;
    }
}

// ---------------------------------------------------------------------------
// Kernel B (R2): recurrence, 2-CTA clusters, k-split, W resident in smem.
//
// 64 clusters x 2 CTAs. Cluster g owns batch rows 4g..4g+3. CTA rank r owns
// output columns [128r, 128r+128). Each CTA keeps its W half (256x128 fp32 =
// 128KB) in smem for the whole kernel -> zero W traffic in the loop.
// h state: double-buffered [256 cols][4 rows] interleaved, exchanged per step
// via DSMEM v4 stores + split cluster barrier.
// Inner product uses packed fma.rn.f32x2 (2 batch rows per instruction).
// ---------------------------------------------------------------------------
#define RROWS 4
#define KH    128                         // cols per CTA
#define HBUF_FLOATS (Ksz * RROWS)         // 1024 floats per h buffer
#define REC_SMEM_BYTES (Ksz * KH * 4 + 2 * HBUF_FLOATS * 4)   // 131072 + 8192

__device__ __forceinline__ unsigned long long pack2(float lo, float hi) {
    unsigned long long r;
    asm("mov.b64 %0, {%1, %2};" : "=l"(r) : "f"(lo), "f"(hi));
    return r;
}
__device__ __forceinline__ void unpack2(unsigned long long v, float& lo, float& hi) {
    asm("mov.b64 {%0, %1}, %2;" : "=f"(lo), "=f"(hi) : "l"(v));
}
__device__ __forceinline__ void fma2(unsigned long long& acc, unsigned long long h, unsigned long long w) {
    asm("fma.rn.f32x2 %0, %1, %2, %0;" : "+l"(acc) : "l"(h), "l"(w));
}
__device__ __forceinline__ void add2(unsigned long long& a, unsigned long long b) {
    asm("add.rn.f32x2 %0, %0, %1;" : "+l"(a) : "l"(b));
}

extern __shared__ float rec_smem[];

__global__ void __launch_bounds__(KH, 1) __cluster_dims__(2, 1, 1)
rnn_rec2_kernel(const float* __restrict__ xU,
                const float* __restrict__ W,
                float* __restrict__ out)
{
    float* Wh = rec_smem;                       // [256][128]
    float* hb = rec_smem + Ksz * KH;            // [2][256][4] interleaved by col

    const int c   = threadIdx.x;                // 0..127 (column within CTA half)
    uint32_t rank;
    asm("mov.u32 %0, %%cluster_ctarank;" : "=r"(rank));
    const uint32_t peer = rank ^ 1u;
    const int c0  = (int)rank * KH;
    const int grp = blockIdx.x >> 1;
    const int b0  = grp * RROWS;

    // Load this CTA's W half into smem: Wh[d][c] = W[d][c0 + c]
    for (int i = c; i < Ksz * (KH / 4); i += KH) {
        int d = i >> 5;                         // 0..255
        int q = (i & 31) << 2;                  // 0..124
        *(float4*)&Wh[d * KH + q] = *(const float4*)&W[(size_t)d * Ksz + c0 + q];
    }
    // Zero both h buffers (covers both halves locally)
    for (int i = c; i < 2 * HBUF_FLOATS; i += KH) hb[i] = 0.0f;
    __syncthreads();
    // Ensure both CTAs finished init before any DSMEM store can land
    asm volatile("barrier.cluster.arrive.aligned;" ::: "memory");
    asm volatile("barrier.cluster.wait.aligned;"   ::: "memory");

    // Precompute smem byte addresses for the h write slots (both buffers),
    // local and peer (via mapa).
    const int cg = c0 + c;                       // global column 0..255
    uint32_t wr_local[2], wr_peer[2];
    #pragma unroll
    for (int p = 0; p < 2; p++) {
        uint32_t a;
        asm("{ .reg .u64 t; cvta.to.shared.u64 t, %1; cvt.u32.u64 %0, t; }"
            : "=r"(a) : "l"(&hb[p * HBUF_FLOATS + cg * RROWS]));
        wr_local[p] = a;
        asm("mapa.shared::cluster.u32 %0, %1, %2;" : "=r"(wr_peer[p]) : "r"(a), "r"(peer));
    }

    // xu pointers (stride Ksz per timestep)
    const float* xp0 = xU + ((size_t)(b0 + 0) * Tsz) * Ksz + cg;
    const float* xp1 = xU + ((size_t)(b0 + 1) * Tsz) * Ksz + cg;
    const float* xp2 = xU + ((size_t)(b0 + 2) * Tsz) * Ksz + cg;
    const float* xp3 = xU + ((size_t)(b0 + 3) * Tsz) * Ksz + cg;

    float xu0 = xp0[0], xu1 = xp1[0], xu2 = xp2[0], xu3 = xp3[0];
    float h0 = 0.f, h1 = 0.f, h2 = 0.f, h3 = 0.f;

    for (int t = 0; t < Tsz; t++) {
        const double2* hrd = (const double2*)(hb + (t & 1) * HBUF_FLOATS);

        unsigned long long a01a = pack2(xu0, xu1);
        unsigned long long a23a = pack2(xu2, xu3);
        unsigned long long a01b = pack2(0.f, 0.f);
        unsigned long long a23b = a01b;

        // Prefetch next step's xu (flies across the barrier)
        {
            int tn = (t + 1 < Tsz) ? t + 1 : t;
            size_t off = (size_t)tn * Ksz;
            xu0 = xp0[off]; xu1 = xp1[off]; xu2 = xp2[off]; xu3 = xp3[off];
        }

        #pragma unroll 4
        for (int d = 0; d < Ksz; d += 2) {
            double2 hA = hrd[d];
            double2 hB = hrd[d + 1];
            float wA = Wh[d * KH + c];
            float wB = Wh[(d + 1) * KH + c];
            unsigned long long wA2 = pack2(wA, wA);
            unsigned long long wB2 = pack2(wB, wB);
            fma2(a01a, __double_as_longlong(hA.x), wA2);
            fma2(a23a, __double_as_longlong(hA.y), wA2);
            fma2(a01b, __double_as_longlong(hB.x), wB2);
            fma2(a23b, __double_as_longlong(hB.y), wB2);
        }

        add2(a01a, a01b);
        add2(a23a, a23b);
        float s0, s1, s2, s3;
        unpack2(a01a, s0, s1);
        unpack2(a23a, s2, s3);
        h0 = tanhf(s0); h1 = tanhf(s1); h2 = tanhf(s2); h3 = tanhf(s3);

        if (t + 1 < Tsz) {
            int p = (t + 1) & 1;   // write buffer = read buffer of step t+1
            asm volatile("st.shared.v4.f32 [%0], {%1, %2, %3, %4};"
                         :: "r"(wr_local[p]), "f"(h0), "f"(h1), "f"(h2), "f"(h3) : "memory");
            asm volatile("st.shared::cluster.v4.f32 [%0], {%1, %2, %3, %4};"
                         :: "r"(wr_peer[p]), "f"(h0), "f"(h1), "f"(h2), "f"(h3) : "memory");
            asm volatile("barrier.cluster.arrive.aligned;" ::: "memory");
            asm volatile("barrier.cluster.wait.aligned;"   ::: "memory");
        }
    }

    // Final state straight from registers
    out[(size_t)(b0 + 0) * Ksz + cg] = h0;
    out[(size_t)(b0 + 1) * Ksz + cg] = h1;
    out[(size_t)(b0 + 2) * Ksz + cg] = h2;
    out[(size_t)(b0 + 3) * Ksz + cg] = h3;
}

// ---------------------------------------------------------------------------
// Launch
// ---------------------------------------------------------------------------
extern "C" void kernel_launch(void* const* d_in, const int* in_sizes, int n_in,
                              void* d_out, int out_size)
{
    const float* x    = (const float*)d_in[0];   // [256, 512, 256]
    const float* U    = (const float*)d_in[1];   // [256, 256]
    const float* W    = (const float*)d_in[2];   // [256, 256]
    const float* bias = (const float*)d_in[3];   // [256]
    float* out        = (float*)d_out;           // [256, 1, 256]

    float* xU;
    cudaGetSymbolAddress((void**)&xU, g_xU);

    dim3 gridA(Ksz / BN, (Bsz * Tsz) / BM);
    gemm_xu_kernel<<<gridA, 256>>>(x, U, bias, xU);

    cudaFuncSetAttribute(rnn_rec2_kernel,
                         cudaFuncAttributeMaxDynamicSharedMemorySize,
                         REC_SMEM_BYTES);
    rnn_rec2_kernel<<<(Bsz / RROWS) * 2, KH, REC_SMEM_BYTES>>>(xU, W, out);
}

// round 4
// speedup vs baseline: 4.6313x; 1.5902x over previous
#include <cuda_runtime.h>
#include <math.h>
#include <stdint.h>

#define Bsz 256
#define Tsz 512
#define Dsz 256
#define Ksz 256

__device__ float g_xU[Bsz * Tsz * Ksz];   // 128 MB scratch for xU = x@U + b

// ===========================================================================
// Helpers
// ===========================================================================
__device__ __forceinline__ unsigned long long pack2(float lo, float hi) {
    unsigned long long r;
    asm("mov.b64 %0, {%1, %2};" : "=l"(r) : "f"(lo), "f"(hi));
    return r;
}
__device__ __forceinline__ void unpack2(unsigned long long v, float& lo, float& hi) {
    asm("mov.b64 {%0, %1}, %2;" : "=f"(lo), "=f"(hi) : "l"(v));
}
__device__ __forceinline__ void fma2(unsigned long long& acc, unsigned long long h, unsigned long long w) {
    asm("fma.rn.f32x2 %0, %1, %2, %0;" : "+l"(acc) : "l"(h), "l"(w));
}
__device__ __forceinline__ void add2(unsigned long long& a, unsigned long long b) {
    asm("add.rn.f32x2 %0, %0, %1;" : "+l"(a) : "l"(b));
}
__device__ __forceinline__ uint32_t f2tf32(float f) {
    uint32_t r;
    asm("cvt.rna.tf32.f32 %0, %1;" : "=r"(r) : "f"(f));
    return r;
}
__device__ __forceinline__ void mma_tf32(float* c, const uint32_t* a, const uint32_t* b) {
    asm("mma.sync.aligned.m16n8k8.row.col.f32.tf32.tf32.f32 "
        "{%0,%1,%2,%3}, {%4,%5,%6,%7}, {%8,%9}, {%0,%1,%2,%3};"
        : "+f"(c[0]), "+f"(c[1]), "+f"(c[2]), "+f"(c[3])
        : "r"(a[0]), "r"(a[1]), "r"(a[2]), "r"(a[3]), "r"(b[0]), "r"(b[1]));
}

// ===========================================================================
// Kernel A: xU = X @ U + b   — tf32 tensor cores (mma.sync m16n8k8)
// Block tile 128x128, BK=32, 8 warps (4m x 2n), warp tile 32x64.
// ===========================================================================
__global__ void __launch_bounds__(256) gemm_xu_tc(
    const float* __restrict__ X,
    const float* __restrict__ U,
    const float* __restrict__ bias,
    float* __restrict__ out)
{
    __shared__ float As[128][36];   // [m][k], pad 36 -> bank = (4m+k)%32 conflict-free
    __shared__ float Bs[32][132];   // [k][n], pad 132 -> bank = (4k+n)%32 conflict-free

    const int tid  = threadIdx.x;
    const int wid  = tid >> 5;
    const int lane = tid & 31;
    const int wm   = (wid & 3) * 32;       // warp m offset in tile
    const int wn   = (wid >> 2) * 64;      // warp n offset in tile
    const int row0 = blockIdx.y * 128;
    const int col0 = blockIdx.x * 128;

    float acc[2][8][4];
    #pragma unroll
    for (int mt = 0; mt < 2; mt++)
        #pragma unroll
        for (int nt = 0; nt < 8; nt++)
            #pragma unroll
            for (int i = 0; i < 4; i++) acc[mt][nt][i] = 0.0f;

    const int ar = lane >> 2;     // 0..7
    const int ac = lane & 3;      // 0..3
    const int bk = lane & 3;      // 0..3
    const int bn = lane >> 2;     // 0..7

    for (int kb = 0; kb < Dsz; kb += 32) {
        // G2S: 4096 floats each for A and B; 256 threads x 4 float4
        #pragma unroll
        for (int i = 0; i < 4; i++) {
            int lin = tid + i * 256;
            int m = lin >> 3, k = (lin & 7) << 2;
            float4 v = *(const float4*)&X[(size_t)(row0 + m) * Dsz + kb + k];
            v.x = __uint_as_float(f2tf32(v.x));
            v.y = __uint_as_float(f2tf32(v.y));
            v.z = __uint_as_float(f2tf32(v.z));
            v.w = __uint_as_float(f2tf32(v.w));
            *(float4*)&As[m][k] = v;

            int k2 = lin >> 5, n = (lin & 31) << 2;
            float4 u = *(const float4*)&U[(size_t)(kb + k2) * Ksz + col0 + n];
            u.x = __uint_as_float(f2tf32(u.x));
            u.y = __uint_as_float(f2tf32(u.y));
            u.z = __uint_as_float(f2tf32(u.z));
            u.w = __uint_as_float(f2tf32(u.w));
            *(float4*)&Bs[k2][n] = u;
        }
        __syncthreads();

        #pragma unroll
        for (int kc = 0; kc < 4; kc++) {
            const int k0 = kc * 8;
            uint32_t af[2][4];
            #pragma unroll
            for (int mt = 0; mt < 2; mt++) {
                const int mb = wm + mt * 16;
                af[mt][0] = __float_as_uint(As[mb + ar    ][k0 + ac    ]);
                af[mt][1] = __float_as_uint(As[mb + ar + 8][k0 + ac    ]);
                af[mt][2] = __float_as_uint(As[mb + ar    ][k0 + ac + 4]);
                af[mt][3] = __float_as_uint(As[mb + ar + 8][k0 + ac + 4]);
            }
            #pragma unroll
            for (int nt = 0; nt < 8; nt++) {
                uint32_t bf[2];
                const int nb = wn + nt * 8 + bn;
                bf[0] = __float_as_uint(Bs[k0 + bk    ][nb]);
                bf[1] = __float_as_uint(Bs[k0 + bk + 4][nb]);
                mma_tf32(acc[0][nt], af[0], bf);
                mma_tf32(acc[1][nt], af[1], bf);
            }
        }
        __syncthreads();
    }

    // Epilogue: add bias, store. c0,c1 at (row, 2*ac), (row, 2*ac+1); c2,c3 at row+8.
    #pragma unroll
    for (int nt = 0; nt < 8; nt++) {
        const int cb = col0 + wn + nt * 8 + 2 * (lane & 3);
        float2 bb = *(const float2*)&bias[cb];
        #pragma unroll
        for (int mt = 0; mt < 2; mt++) {
            const int r = row0 + wm + mt * 16 + (lane >> 2);
            float2 o0 = { acc[mt][nt][0] + bb.x, acc[mt][nt][1] + bb.y };
            float2 o1 = { acc[mt][nt][2] + bb.x, acc[mt][nt][3] + bb.y };
            *(float2*)&out[(size_t)r       * Ksz + cb] = o0;
            *(float2*)&out[(size_t)(r + 8) * Ksz + cb] = o1;
        }
    }
}

// ===========================================================================
// Kernel B (R3): recurrence. 64 clusters x 2 CTAs x 256 threads.
// W lives in REGISTERS (128 per thread). smem holds only the h state (8KB)
// plus 2KB reduction scratch -> crossbar traffic halved vs R2.
// Thread (c, hh): column c of CTA half, d-half hh. hh=0 <-> locally-produced
// d range (computes before cluster wait, hiding UCGABAR_WAIT behind the
// peer-half warps on the same SMSP).
// ===========================================================================
#define RROWS 4

__global__ void __launch_bounds__(256, 1) __cluster_dims__(2, 1, 1)
rnn_rec3_kernel(const float* __restrict__ xU,
                const float* __restrict__ W,
                float* __restrict__ out)
{
    __shared__ float hb[2][Ksz * RROWS];        // [buf][d*4 + r]  (8 KB)
    __shared__ ulonglong2 red[128];             // cross-half reduction scratch

    const int tid = threadIdx.x;
    const int c   = tid & 127;
    const int hh  = tid >> 7;                   // 0: local-d half, 1: peer-d half
    uint32_t rank;
    asm("mov.u32 %0, %%cluster_ctarank;" : "=r"(rank));
    const uint32_t peer = rank ^ 1u;
    const int c0 = (int)rank << 7;
    const int cg = c0 + c;                      // global column
    const int d0 = ((hh ^ (int)rank) << 7);     // hh=0 -> own cols' d range
    const int b0 = (blockIdx.x >> 1) * RROWS;

    // W column slice into registers
    float Wreg[128];
    #pragma unroll
    for (int j = 0; j < 128; j++)
        Wreg[j] = W[(size_t)(d0 + j) * Ksz + cg];

    // zero h buffers
    for (int i = tid; i < 2 * Ksz * RROWS; i += 256)
        hb[0][i] = 0.0f;   // hb is contiguous: [0] spans both buffers via flat index
    __syncthreads();
    asm volatile("barrier.cluster.arrive;" ::: "memory");   // round 0
    asm volatile("barrier.cluster.wait;"   ::: "memory");

    // h write addresses (local + peer via mapa), used by hh==0 threads
    uint32_t wrL[2], wrP[2];
    #pragma unroll
    for (int p = 0; p < 2; p++) {
        uint32_t a;
        asm("{ .reg .u64 t; cvta.to.shared.u64 t, %1; cvt.u32.u64 %0, t; }"
            : "=r"(a) : "l"(&hb[p][cg * RROWS]));
        wrL[p] = a;
        asm("mapa.shared::cluster.u32 %0, %1, %2;" : "=r"(wrP[p]) : "r"(a), "r"(peer));
    }

    // xu pointers + first prefetch (hh==0 threads consume xu)
    const float* xp0 = xU + ((size_t)(b0 + 0) * Tsz) * Ksz + cg;
    const float* xp1 = xU + ((size_t)(b0 + 1) * Tsz) * Ksz + cg;
    const float* xp2 = xU + ((size_t)(b0 + 2) * Tsz) * Ksz + cg;
    const float* xp3 = xU + ((size_t)(b0 + 3) * Tsz) * Ksz + cg;
    float xu0 = 0.f, xu1 = 0.f, xu2 = 0.f, xu3 = 0.f;
    if (hh == 0) { xu0 = xp0[0]; xu1 = xp1[0]; xu2 = xp2[0]; xu3 = xp3[0]; }

    float h0 = 0.f, h1 = 0.f, h2 = 0.f, h3 = 0.f;

    for (int t = 0; t < Tsz; t++) {
        // peer-half warps wait first; local-half warps compute first (overlap)
        if (hh == 1 && t > 0)
            asm volatile("barrier.cluster.wait;" ::: "memory");

        const double2* hrd = (const double2*)&hb[t & 1][d0 * RROWS];
        unsigned long long p01 = pack2(0.f, 0.f);
        unsigned long long p23 = p01;
        #pragma unroll
        for (int j = 0; j < 128; j++) {
            double2 hd = hrd[j];
            unsigned long long w2 = pack2(Wreg[j], Wreg[j]);
            fma2(p01, __double_as_longlong(hd.x), w2);
            fma2(p23, __double_as_longlong(hd.y), w2);
        }

        if (hh == 0 && t > 0)
            asm volatile("barrier.cluster.wait;" ::: "memory");

        if (hh == 1) red[c] = make_ulonglong2(p01, p23);
        __syncthreads();                       // sync1: partials visible

        if (hh == 0) {
            ulonglong2 q = red[c];
            add2(p01, q.x);
            add2(p23, q.y);
            add2(p01, pack2(xu0, xu1));
            add2(p23, pack2(xu2, xu3));
            // prefetch next step's xu (consumed next iteration)
            {
                int tn = (t + 1 < Tsz) ? t + 1 : t;
                size_t off = (size_t)tn * Ksz;
                xu0 = xp0[off]; xu1 = xp1[off]; xu2 = xp2[off]; xu3 = xp3[off];
            }
            float s0, s1, s2, s3;
            unpack2(p01, s0, s1);
            unpack2(p23, s2, s3);
            h0 = tanhf(s0); h1 = tanhf(s1); h2 = tanhf(s2); h3 = tanhf(s3);

            if (t + 1 < Tsz) {
                int p = (t + 1) & 1;
                asm volatile("st.shared.v4.f32 [%0], {%1, %2, %3, %4};"
                             :: "r"(wrL[p]), "f"(h0), "f"(h1), "f"(h2), "f"(h3) : "memory");
                asm volatile("st.shared::cluster.v4.f32 [%0], {%1, %2, %3, %4};"
                             :: "r"(wrP[p]), "f"(h0), "f"(h1), "f"(h2), "f"(h3) : "memory");
            }
        }
        asm volatile("barrier.cluster.arrive;" ::: "memory");  // round t+1
        __syncthreads();                       // sync2: local h writes visible
    }

    if (hh == 0) {
        out[(size_t)(b0 + 0) * Ksz + cg] = h0;
        out[(size_t)(b0 + 1) * Ksz + cg] = h1;
        out[(size_t)(b0 + 2) * Ksz + cg] = h2;
        out[(size_t)(b0 + 3) * Ksz + cg] = h3;
    }
}

// ===========================================================================
// Launch
// ===========================================================================
extern "C" void kernel_launch(void* const* d_in, const int* in_sizes, int n_in,
                              void* d_out, int out_size)
{
    const float* x    = (const float*)d_in[0];   // [256, 512, 256]
    const float* U    = (const float*)d_in[1];   // [256, 256]
    const float* W    = (const float*)d_in[2];   // [256, 256]
    const float* bias = (const float*)d_in[3];   // [256]
    float* out        = (float*)d_out;           // [256, 1, 256]

    float* xU;
    cudaGetSymbolAddress((void**)&xU, g_xU);

    dim3 gridA(Ksz / 128, (Bsz * Tsz) / 128);    // (2, 1024)
    gemm_xu_tc<<<gridA, 256>>>(x, U, bias, xU);

    rnn_rec3_kernel<<<(Bsz / RROWS) * 2, 256>>>(xU, W, out);
}